// round 8
// baseline (speedup 1.0000x reference)
#include <cuda_runtime.h>
#include <cuda_fp16.h>

// In (4,8,262144) f32, NNsites (13,262144) i32, Weights (8,8,16) f32,
// bias (8,8) f32. Output (4,8,262144) f32.
#define NSITES_MAX 262144

// Site-major features, fp16, PRE-SCALED by log2(e). Row = 32 half = 64 B.
// g_T[n][bo] = log2e *  sum_i Wn[o][i]*In[b][i][n]
// g_S[n][bo] = log2e * (sum_i Ws[o][i]*In[b][i][n] + beff[o])
__device__ __align__(256) __half2 g_T[NSITES_MAX * 16];
__device__ __align__(256) __half2 g_S[NSITES_MAX * 16];

__device__ __forceinline__ __half2 u32_as_h2(unsigned v) {
    return *reinterpret_cast<const __half2*>(&v);
}

// acc (packed f32x2) += {a, b}
__device__ __forceinline__ void acc_f32x2(unsigned long long& acc, float a, float b) {
    unsigned long long t;
    asm("mov.b64 %0, {%1, %2};" : "=l"(t) : "f"(a), "f"(b));
    asm("add.rn.f32x2 %0, %0, %1;" : "+l"(acc) : "l"(t));
}
__device__ __forceinline__ void unpack_f32x2(unsigned long long v, float& lo, float& hi) {
    asm("mov.b64 {%0, %1}, %2;" : "=f"(lo), "=f"(hi) : "l"(v));
}

// ---------------------------------------------------------------------------
// Pass 1: compute BOTH T' and S' (fp16, log2e-scaled), site-major.
// R6 scalar structure, 64 sites/CTA (grid 4096) for better latency overlap.
// ---------------------------------------------------------------------------
__global__ __launch_bounds__(256) void pass1_kernel(
    const float* __restrict__ In,      // In[(b*8+i)*N + n]
    const float* __restrict__ W,       // W[j*128 + o*16 + k]
    const float* __restrict__ bias,    // bias[j*8 + o]
    int N)
{
    __shared__ float sWn[8][8];
    __shared__ float sWs[8][8];
    __shared__ float sbe[8];
    __shared__ float sin_[32][65];

    const int tid  = threadIdx.x;
    const int base = blockIdx.x * 64;

    if (tid < 64) {
        int o = tid >> 3, i = tid & 7;
        float wn = 0.f, ws = 0.f;
        #pragma unroll
        for (int j = 0; j < 8; j++) {
            ws += W[j * 128 + o * 16 + i];
            wn += W[j * 128 + o * 16 + 8 + i];
        }
        sWn[o][i] = wn * 1.44269504f;   // fold log2e
        sWs[o][i] = ws * 1.44269504f;
        if (i == 0) {
            float be = 0.f;
            #pragma unroll
            for (int j = 0; j < 8; j++) be += bias[j * 8 + o];
            sbe[o] = be * 1.44269504f;
        }
    }
    #pragma unroll
    for (int k = 0; k < 8; k++) {
        int idx = tid + k * 256;
        int r = idx >> 6, c = idx & 63;
        sin_[r][c] = In[r * N + base + c];
    }
    __syncthreads();

    const int w  = tid >> 5, lane = tid & 31;
    const int j  = lane & 7;                // bo group: 4j..4j+3
    const int b  = j >> 1, o0 = (j & 1) * 4;

    #pragma unroll
    for (int st = 0; st < 2; st++) {
        const int sl = st * 32 + w * 4 + (lane >> 3);

        float x[8];
        #pragma unroll
        for (int i = 0; i < 8; i++) x[i] = sin_[b * 8 + i][sl];

        float tv[4], sv[4];
        #pragma unroll
        for (int q = 0; q < 4; q++) {
            float at = 0.f, as = sbe[o0 + q];
            #pragma unroll
            for (int i = 0; i < 8; i++) {
                at = fmaf(sWn[o0 + q][i], x[i], at);
                as = fmaf(sWs[o0 + q][i], x[i], as);
            }
            tv[q] = at; sv[q] = as;
        }
        __half2 th0 = __floats2half2_rn(tv[0], tv[1]);
        __half2 th1 = __floats2half2_rn(tv[2], tv[3]);
        __half2 sh0 = __floats2half2_rn(sv[0], sv[1]);
        __half2 sh1 = __floats2half2_rn(sv[2], sv[3]);
        uint2 ut = make_uint2(*reinterpret_cast<unsigned*>(&th0),
                              *reinterpret_cast<unsigned*>(&th1));
        uint2 us = make_uint2(*reinterpret_cast<unsigned*>(&sh0),
                              *reinterpret_cast<unsigned*>(&sh1));
        ((uint2*)g_T)[(base + sl) * 8 + j] = ut;
        ((uint2*)g_S)[(base + sl) * 8 + j] = us;
    }
}

// ---------------------------------------------------------------------------
// Pass 2: out[bo][n] = sum_z softplus(S + T[nn]); log2e-scaled:
//   sum sp(x) = ln2 * sum max(x',0) + log( prod (1+2^{-|x'|}) )
// NO shared memory, NO barriers. 4 lanes/site, 8 sites/warp, LDG.128 gathers.
// launch_bounds(256,8): force <=32 regs for 100% theoretical occupancy.
// ---------------------------------------------------------------------------
__global__ __launch_bounds__(256, 8) void pass2_kernel(
    const int*   __restrict__ NN,      // NN[z*N + n]
    float*       __restrict__ out,     // out[bo*N + n]
    int N)
{
    const int tid  = threadIdx.x;
    const int base = blockIdx.x * 64;
    const int w    = tid >> 5, lane = tid & 31;
    const int sl   = w * 8 + (lane >> 2);
    const int jj   = lane & 3;              // batch b; bo = jj*8..jj*8+7
    const int n    = base + sl;

    uint4 s4 = ((const uint4*)g_S)[n * 4 + jj];
    __half2 s2[4] = { u32_as_h2(s4.x), u32_as_h2(s4.y),
                      u32_as_h2(s4.z), u32_as_h2(s4.w) };

    const __half2 one2 = __float2half2_rn(1.f);
    const __half2 m22  = __float2half2_rn(-2.f);
    const uint4* __restrict__ Tp = (const uint4*)g_T;

    __half2 prod[4] = {one2, one2, one2, one2};
    unsigned long long lin[4] = {0ull, 0ull, 0ull, 0ull};

    #pragma unroll
    for (int zc = 0; zc < 3; zc++) {
        int idx[4];
        #pragma unroll
        for (int z = 0; z < 4; z++)
            idx[z] = NN[(zc * 4 + z + 1) * N + n];
        uint4 t4[4];
        #pragma unroll
        for (int z = 0; z < 4; z++)
            t4[z] = Tp[idx[z] * 4 + jj];
        #pragma unroll
        for (int p = 0; p < 2; p++) {
            const uint4& ta = t4[p * 2];
            const uint4& tb = t4[p * 2 + 1];
            unsigned tau[4] = {ta.x, ta.y, ta.z, ta.w};
            unsigned tbu[4] = {tb.x, tb.y, tb.z, tb.w};
            #pragma unroll
            for (int m = 0; m < 4; m++) {
                __half2 tha = u32_as_h2(tau[m]);
                __half2 thb = u32_as_h2(tbu[m]);
                __half2 ra = __hfma2_relu(s2[m], one2, tha);          // max(x',0)
                __half2 rb = __hfma2_relu(s2[m], one2, thb);
                __half2 ma = __hadd2(__hfma2(ra, m22, tha), s2[m]);   // -|x'|
                __half2 mb = __hadd2(__hfma2(rb, m22, thb), s2[m]);
                __half2 e;
                e = h2exp2(ma); prod[m] = __hfma2(prod[m], e, prod[m]);
                e = h2exp2(mb); prod[m] = __hfma2(prod[m], e, prod[m]);
                __half2 rp = __hadd2(ra, rb);        // pair-sum in f16
                float2 f = __half22float2(rp);
                acc_f32x2(lin[m], f.x, f.y);
            }
        }
    }

    const float ln2 = 0.69314718f;
    #pragma unroll
    for (int m = 0; m < 4; m++) {
        float lx, ly;
        unpack_f32x2(lin[m], lx, ly);
        float r0 = fmaf(ln2, lx, __logf(__low2float (prod[m])));
        float r1 = fmaf(ln2, ly, __logf(__high2float(prod[m])));
        out[(jj * 8 + 2 * m + 0) * N + n] = r0;   // 8 lanes -> 8 consecutive n
        out[(jj * 8 + 2 * m + 1) * N + n] = r1;
    }
}

extern "C" void kernel_launch(void* const* d_in, const int* in_sizes, int n_in,
                              void* d_out, int out_size)
{
    const float* In   = (const float*)d_in[0];
    const int*   NN   = (const int*)  d_in[1];
    const float* W    = (const float*)d_in[2];
    const float* bias = (const float*)d_in[3];
    float*       out  = (float*)d_out;

    const int N = in_sizes[0] / 32;

    pass1_kernel<<<N / 64, 256>>>(In, W, bias, N);
    pass2_kernel<<<N / 64, 256>>>(NN, out, N);
}

// round 9
// speedup vs baseline: 1.0956x; 1.0956x over previous
#include <cuda_runtime.h>
#include <cuda_fp16.h>

// In (4,8,262144) f32, NNsites (13,262144) i32, Weights (8,8,16) f32,
// bias (8,8) f32. Output (4,8,262144) f32.
#define NSITES_MAX 262144

// Site-major neighbor features, fp16, PRE-SCALED by log2(e). Row = 32 half = 64B.
__device__ __align__(256) __half2 g_T[NSITES_MAX * 16];

// Pre-reduced self weights / bias (log2e-scaled), produced by pass0.
__device__ __align__(16) float g_Wsp[64];   // [o][i], Ws'[o][i] = log2e * sum_j W[j,o,i]
__device__ __align__(16) float g_bep[8];    // log2e * sum_j bias[j,o]

__device__ __forceinline__ __half2 u32_as_h2(unsigned v) {
    return *reinterpret_cast<const __half2*>(&v);
}
__device__ __forceinline__ void acc_f32x2(unsigned long long& acc, float a, float b) {
    unsigned long long t;
    asm("mov.b64 %0, {%1, %2};" : "=l"(t) : "f"(a), "f"(b));
    asm("add.rn.f32x2 %0, %0, %1;" : "+l"(acc) : "l"(t));
}
__device__ __forceinline__ void unpack_f32x2(unsigned long long v, float& lo, float& hi) {
    asm("mov.b64 {%0, %1}, %2;" : "=f"(lo), "=f"(hi) : "l"(v));
}

// ---------------------------------------------------------------------------
// Pass 0: reduce self-weights + bias over axis j (one tiny block).
// ---------------------------------------------------------------------------
__global__ void pass0_kernel(const float* __restrict__ W,
                             const float* __restrict__ bias)
{
    const int t = threadIdx.x;            // 64 threads
    const int o = t >> 3, i = t & 7;
    float ws = 0.f;
    #pragma unroll
    for (int j = 0; j < 8; j++) ws += W[j * 128 + o * 16 + i];
    g_Wsp[o * 8 + i] = ws * 1.44269504f;
    if (i == 0) {
        float be = 0.f;
        #pragma unroll
        for (int j = 0; j < 8; j++) be += bias[j * 8 + o];
        g_bep[o] = be * 1.44269504f;
    }
}

// ---------------------------------------------------------------------------
// Pass 1: T'[n][bo] = log2e * sum_i Wn[o][i]*In[b][i][n], fp16 (R5 structure).
// 128 sites/CTA, float4 tile loads, smem row stride 132 (16B-aligned rows).
// ---------------------------------------------------------------------------
__global__ __launch_bounds__(256) void pass1_kernel(
    const float* __restrict__ In,      // In[(b*8+i)*N + n]
    const float* __restrict__ W,       // W[j*128 + o*16 + k]
    int N)
{
    __shared__ float sWn[8][8];
    __shared__ float sin_[32][132];

    const int tid  = threadIdx.x;
    const int base = blockIdx.x * 128;

    if (tid < 64) {
        int o = tid >> 3, i = tid & 7;
        float wn = 0.f;
        #pragma unroll
        for (int j = 0; j < 8; j++) wn += W[j * 128 + o * 16 + 8 + i];
        sWn[o][i] = wn * 1.44269504f;   // fold log2e
    }
    // 32 rows x 128 cols, float4: 1024 vec loads, 4 per thread.
    #pragma unroll
    for (int k = 0; k < 4; k++) {
        int idx = tid + k * 256;
        int r = idx >> 5, c4 = (idx & 31) * 4;
        float4 v = *(const float4*)&In[r * N + base + c4];
        *(float4*)&sin_[r][c4] = v;
    }
    __syncthreads();

    const int w  = tid >> 5, lane = tid & 31;
    const int j  = lane & 7;                // bo group: 4j..4j+3
    const int b  = j >> 1, o0 = (j & 1) * 4;

    #pragma unroll
    for (int st = 0; st < 4; st++) {
        const int sl = st * 32 + w * 4 + (lane >> 3);

        float x[8];
        #pragma unroll
        for (int i = 0; i < 8; i++) x[i] = sin_[b * 8 + i][sl];

        float tv[4];
        #pragma unroll
        for (int q = 0; q < 4; q++) {
            float acc = 0.f;
            #pragma unroll
            for (int i = 0; i < 8; i++) acc = fmaf(sWn[o0 + q][i], x[i], acc);
            tv[q] = acc;
        }
        __half2 h0 = __floats2half2_rn(tv[0], tv[1]);
        __half2 h1 = __floats2half2_rn(tv[2], tv[3]);
        uint2 u = make_uint2(*reinterpret_cast<unsigned*>(&h0),
                             *reinterpret_cast<unsigned*>(&h1));
        ((uint2*)g_T)[(base + sl) * 8 + j] = u;
    }
}

// ---------------------------------------------------------------------------
// Pass 2: out[bo][n] = sum_z softplus(S + T[nn]); log2e-scaled:
//   sum sp(x) = ln2 * sum max(x',0) + log( prod (1+2^{-|x'|}) )
// NO smem, NO barriers. 4 lanes/site (jj = b), 8 sites/warp.
// S recomputed per-thread: 8 coalesced In loads + 64 FMA, weights via
// warp-uniform float4 LDG from g_Wsp (precomputed by pass0).
// ---------------------------------------------------------------------------
__global__ __launch_bounds__(256, 5) void pass2_kernel(
    const float* __restrict__ In,
    const int*   __restrict__ NN,      // NN[z*N + n]
    float*       __restrict__ out,     // out[bo*N + n]
    int N)
{
    const int tid  = threadIdx.x;
    const int base = blockIdx.x * 64;
    const int w    = tid >> 5, lane = tid & 31;
    const int sl   = w * 8 + (lane >> 2);
    const int jj   = lane & 3;              // batch b; bo = jj*8..jj*8+7
    const int n    = base + sl;

    // Kick off the DRAM-latency loads first.
    int idx[12];
    #pragma unroll
    for (int z = 0; z < 12; z++) idx[z] = __ldg(&NN[(z + 1) * N + n]);

    float x[8];
    #pragma unroll
    for (int i = 0; i < 8; i++) x[i] = __ldg(&In[(jj * 8 + i) * N + n]);

    // Recompute S' (log2e-scaled) for 8 bo under the NN-load shadow.
    const float4* __restrict__ Wv = (const float4*)g_Wsp;   // [o][i] rows
    const float4* __restrict__ Bv = (const float4*)g_bep;
    float4 be0 = __ldg(&Bv[0]), be1 = __ldg(&Bv[1]);
    float bev[8] = {be0.x, be0.y, be0.z, be0.w, be1.x, be1.y, be1.z, be1.w};

    __half2 s2[4];
    #pragma unroll
    for (int m = 0; m < 4; m++) {
        int q0 = 2 * m, q1 = 2 * m + 1;
        float4 wa0 = __ldg(&Wv[q0 * 2]), wa1 = __ldg(&Wv[q0 * 2 + 1]);
        float4 wb0 = __ldg(&Wv[q1 * 2]), wb1 = __ldg(&Wv[q1 * 2 + 1]);
        float a = bev[q0], c = bev[q1];
        a = fmaf(wa0.x, x[0], a); a = fmaf(wa0.y, x[1], a);
        a = fmaf(wa0.z, x[2], a); a = fmaf(wa0.w, x[3], a);
        a = fmaf(wa1.x, x[4], a); a = fmaf(wa1.y, x[5], a);
        a = fmaf(wa1.z, x[6], a); a = fmaf(wa1.w, x[7], a);
        c = fmaf(wb0.x, x[0], c); c = fmaf(wb0.y, x[1], c);
        c = fmaf(wb0.z, x[2], c); c = fmaf(wb0.w, x[3], c);
        c = fmaf(wb1.x, x[4], c); c = fmaf(wb1.y, x[5], c);
        c = fmaf(wb1.z, x[6], c); c = fmaf(wb1.w, x[7], c);
        s2[m] = __floats2half2_rn(a, c);
    }

    const __half2 one2 = __float2half2_rn(1.f);
    const __half2 m22  = __float2half2_rn(-2.f);
    const uint4* __restrict__ Tp = (const uint4*)g_T;

    __half2 prod[4] = {one2, one2, one2, one2};
    unsigned long long lin[4] = {0ull, 0ull, 0ull, 0ull};

    #pragma unroll
    for (int zc = 0; zc < 3; zc++) {
        uint4 t4[4];
        #pragma unroll
        for (int z = 0; z < 4; z++)
            t4[z] = Tp[idx[zc * 4 + z] * 4 + jj];   // 64B row gather
        #pragma unroll
        for (int p = 0; p < 2; p++) {
            const uint4& ta = t4[p * 2];
            const uint4& tb = t4[p * 2 + 1];
            unsigned tau[4] = {ta.x, ta.y, ta.z, ta.w};
            unsigned tbu[4] = {tb.x, tb.y, tb.z, tb.w};
            #pragma unroll
            for (int m = 0; m < 4; m++) {
                __half2 tha = u32_as_h2(tau[m]);
                __half2 thb = u32_as_h2(tbu[m]);
                __half2 ra = __hfma2_relu(s2[m], one2, tha);          // max(x',0)
                __half2 rb = __hfma2_relu(s2[m], one2, thb);
                __half2 ma = __hadd2(__hfma2(ra, m22, tha), s2[m]);   // -|x'|
                __half2 mb = __hadd2(__hfma2(rb, m22, thb), s2[m]);
                __half2 e;
                e = h2exp2(ma); prod[m] = __hfma2(prod[m], e, prod[m]);
                e = h2exp2(mb); prod[m] = __hfma2(prod[m], e, prod[m]);
                __half2 rp = __hadd2(ra, rb);        // pair-sum in f16
                float2 f = __half22float2(rp);
                acc_f32x2(lin[m], f.x, f.y);
            }
        }
    }

    const float ln2 = 0.69314718f;
    #pragma unroll
    for (int m = 0; m < 4; m++) {
        float lx, ly;
        unpack_f32x2(lin[m], lx, ly);
        float r0 = fmaf(ln2, lx, __logf(__low2float (prod[m])));
        float r1 = fmaf(ln2, ly, __logf(__high2float(prod[m])));
        out[(jj * 8 + 2 * m + 0) * N + n] = r0;   // 8 lanes -> 8 consecutive n
        out[(jj * 8 + 2 * m + 1) * N + n] = r1;
    }
}

extern "C" void kernel_launch(void* const* d_in, const int* in_sizes, int n_in,
                              void* d_out, int out_size)
{
    const float* In   = (const float*)d_in[0];
    const int*   NN   = (const int*)  d_in[1];
    const float* W    = (const float*)d_in[2];
    const float* bias = (const float*)d_in[3];
    float*       out  = (float*)d_out;

    const int N = in_sizes[0] / 32;

    pass0_kernel<<<1, 64>>>(W, bias);
    pass1_kernel<<<N / 128, 256>>>(In, W, N);
    pass2_kernel<<<N / 64, 256>>>(In, NN, out, N);
}

// round 10
// speedup vs baseline: 1.1422x; 1.0426x over previous
#include <cuda_runtime.h>
#include <cuda_fp16.h>

// In (4,8,262144) f32, NNsites (13,262144) i32, Weights (8,8,16) f32,
// bias (8,8) f32. Output (4,8,262144) f32.
#define NSITES_MAX 262144

// Site-major features, fp16, PRE-SCALED by log2(e). Row = 32 half = 64 B.
// g_T[n][bo] = log2e *  sum_i Wn[o][i]*In[b][i][n]
// g_S[n][bo] = log2e * (sum_i Ws[o][i]*In[b][i][n] + beff[o])
__device__ __align__(256) __half2 g_T[NSITES_MAX * 16];
__device__ __align__(256) __half2 g_S[NSITES_MAX * 16];

__device__ __forceinline__ __half2 u32_as_h2(unsigned v) {
    return *reinterpret_cast<const __half2*>(&v);
}

// ---------------------------------------------------------------------------
// Pass 1: streaming T' + S' (fp16, log2e-scaled), site-major, NO data tile.
// Lane = (site, jj): 8 sites x 4 batches per warp. Each thread:
//   8 coalesced In loads -> 8 T + 8 S (128 FMA, weights via LDS.64 bcast)
//   -> one uint4 store per array (warp: 512B contiguous each).
// Only the 64-float weight reduction sits behind the single barrier.
// ---------------------------------------------------------------------------
__global__ __launch_bounds__(256) void pass1_kernel(
    const float* __restrict__ In,      // In[(b*8+i)*N + n]
    const float* __restrict__ W,       // W[j*128 + o*16 + k]
    const float* __restrict__ bias,    // bias[j*8 + o]
    int N)
{
    __shared__ float2 sw[8][8];        // {wn', ws'} per (o,i)
    __shared__ float  sbe[8];

    const int tid  = threadIdx.x;
    const int base = blockIdx.x * 64;
    const float L2E = 1.44269504f;

    if (tid < 64) {
        int o = tid >> 3, i = tid & 7;
        float wn = 0.f, ws = 0.f;
        #pragma unroll
        for (int j = 0; j < 8; j++) {
            ws += W[j * 128 + o * 16 + i];
            wn += W[j * 128 + o * 16 + 8 + i];
        }
        sw[o][i] = make_float2(wn * L2E, ws * L2E);
        if (i == 0) {
            float be = 0.f;
            #pragma unroll
            for (int j = 0; j < 8; j++) be += bias[j * 8 + o];
            sbe[o] = be * L2E;
        }
    }
    __syncthreads();

    const int w    = tid >> 5, lane = tid & 31;
    const int sl   = w * 8 + (lane >> 2);   // site within 64-tile
    const int jj   = lane & 3;              // batch b
    const int n    = base + sl;

    float x[8];
    #pragma unroll
    for (int i = 0; i < 8; i++) x[i] = In[(jj * 8 + i) * N + n];

    float tv[8], sv[8];
    #pragma unroll
    for (int o = 0; o < 8; o++) {
        float at = 0.f, as = sbe[o];
        #pragma unroll
        for (int i = 0; i < 8; i++) {
            float2 wv = sw[o][i];           // LDS.64 broadcast
            at = fmaf(wv.x, x[i], at);
            as = fmaf(wv.y, x[i], as);
        }
        tv[o] = at; sv[o] = as;
    }

    __half2 th[4], sh[4];
    #pragma unroll
    for (int m = 0; m < 4; m++) {
        th[m] = __floats2half2_rn(tv[2 * m], tv[2 * m + 1]);
        sh[m] = __floats2half2_rn(sv[2 * m], sv[2 * m + 1]);
    }
    uint4 ut = make_uint4(*reinterpret_cast<unsigned*>(&th[0]),
                          *reinterpret_cast<unsigned*>(&th[1]),
                          *reinterpret_cast<unsigned*>(&th[2]),
                          *reinterpret_cast<unsigned*>(&th[3]));
    uint4 us = make_uint4(*reinterpret_cast<unsigned*>(&sh[0]),
                          *reinterpret_cast<unsigned*>(&sh[1]),
                          *reinterpret_cast<unsigned*>(&sh[2]),
                          *reinterpret_cast<unsigned*>(&sh[3]));
    ((uint4*)g_T)[n * 4 + jj] = ut;    // bo = jj*8 .. jj*8+7
    ((uint4*)g_S)[n * 4 + jj] = us;
}

// ---------------------------------------------------------------------------
// Pass 2 (R6 structure): out[bo][n] = sum_z softplus(S + T[nn]); log2e-scaled:
//   sum sp(x) = ln2 * sum max(x',0) + log( prod (1+2^{-|x'|}) )
// NO smem, NO barriers. 4 lanes/site, 8 sites/warp, LDG.128 gathers.
// lin accumulated with scalar FADDs (no 64-bit reg-pairing MOV fat).
// ---------------------------------------------------------------------------
__global__ __launch_bounds__(256, 6) void pass2_kernel(
    const int*   __restrict__ NN,      // NN[z*N + n]
    float*       __restrict__ out,     // out[bo*N + n]
    int N)
{
    const int tid  = threadIdx.x;
    const int base = blockIdx.x * 64;
    const int w    = tid >> 5, lane = tid & 31;
    const int sl   = w * 8 + (lane >> 2);
    const int jj   = lane & 3;              // batch b; bo = jj*8..jj*8+7
    const int n    = base + sl;

    uint4 s4 = ((const uint4*)g_S)[n * 4 + jj];
    __half2 s2[4] = { u32_as_h2(s4.x), u32_as_h2(s4.y),
                      u32_as_h2(s4.z), u32_as_h2(s4.w) };

    int idx[12];
    #pragma unroll
    for (int z = 0; z < 12; z++) idx[z] = NN[(z + 1) * N + n];

    const __half2 one2 = __float2half2_rn(1.f);
    const __half2 m22  = __float2half2_rn(-2.f);
    const uint4* __restrict__ Tp = (const uint4*)g_T;

    __half2 prod[4] = {one2, one2, one2, one2};
    float lin[8] = {0.f, 0.f, 0.f, 0.f, 0.f, 0.f, 0.f, 0.f};

    #pragma unroll
    for (int zc = 0; zc < 3; zc++) {
        uint4 t4[4];
        #pragma unroll
        for (int z = 0; z < 4; z++)
            t4[z] = Tp[idx[zc * 4 + z] * 4 + jj];   // 64B row gather
        #pragma unroll
        for (int p = 0; p < 2; p++) {
            const uint4& ta = t4[p * 2];
            const uint4& tb = t4[p * 2 + 1];
            unsigned tau[4] = {ta.x, ta.y, ta.z, ta.w};
            unsigned tbu[4] = {tb.x, tb.y, tb.z, tb.w};
            #pragma unroll
            for (int m = 0; m < 4; m++) {
                __half2 tha = u32_as_h2(tau[m]);
                __half2 thb = u32_as_h2(tbu[m]);
                __half2 ra = __hfma2_relu(s2[m], one2, tha);          // max(x',0)
                __half2 rb = __hfma2_relu(s2[m], one2, thb);
                __half2 ma = __hadd2(__hfma2(ra, m22, tha), s2[m]);   // -|x'|
                __half2 mb = __hadd2(__hfma2(rb, m22, thb), s2[m]);
                __half2 e;
                e = h2exp2(ma); prod[m] = __hfma2(prod[m], e, prod[m]);
                e = h2exp2(mb); prod[m] = __hfma2(prod[m], e, prod[m]);
                __half2 rp = __hadd2(ra, rb);        // pair-sum in f16
                float2 f = __half22float2(rp);
                lin[2 * m + 0] += f.x;               // scalar FADD
                lin[2 * m + 1] += f.y;
            }
        }
    }

    const float ln2 = 0.69314718f;
    #pragma unroll
    for (int m = 0; m < 4; m++) {
        float r0 = fmaf(ln2, lin[2 * m + 0], __logf(__low2float (prod[m])));
        float r1 = fmaf(ln2, lin[2 * m + 1], __logf(__high2float(prod[m])));
        out[(jj * 8 + 2 * m + 0) * N + n] = r0;   // 8 lanes -> 8 consecutive n
        out[(jj * 8 + 2 * m + 1) * N + n] = r1;
    }
}

extern "C" void kernel_launch(void* const* d_in, const int* in_sizes, int n_in,
                              void* d_out, int out_size)
{
    const float* In   = (const float*)d_in[0];
    const int*   NN   = (const int*)  d_in[1];
    const float* W    = (const float*)d_in[2];
    const float* bias = (const float*)d_in[3];
    float*       out  = (float*)d_out;

    const int N = in_sizes[0] / 32;

    pass1_kernel<<<N / 64, 256>>>(In, W, bias, N);
    pass2_kernel<<<N / 64, 256>>>(NN, out, N);
}